// round 13
// baseline (speedup 1.0000x reference)
#include <cuda_runtime.h>
#include <cuda_fp16.h>
#include <math.h>
#include <stdint.h>

// Problem shape (fixed)
#define BB 8
#define LL 2048
#define DD 1024
#define NH 16
#define HD 64
#define MTOK (BB * LL)        // 16384 tokens
#define NQKV (3 * DD)         // 3072: fused q|k|v output width

// ======================= scratch ============================================
__device__ __half g_QKV[(size_t)MTOK * NQKV];     // 96 MB fp16 (q|k|v per row)
__device__ __half g_Ah[(size_t)MTOK * DD];        // 32 MB fp16 activations
__device__ __half g_Wh[4ULL * DD * DD];           // 8 MB fp16 weights (transposed)
__device__ float  g_bqkv[NQKV];

// ======================= small helpers ======================================
__device__ __forceinline__ uint32_t smem_u32(const void* p) {
    uint32_t a;
    asm("{ .reg .u64 t; cvta.to.shared.u64 t, %1; cvt.u32.u64 %0, t; }"
        : "=r"(a) : "l"(p));
    return a;
}
__device__ __forceinline__ void cp_async16(uint32_t dst, const void* src) {
    asm volatile("cp.async.cg.shared.global [%0], [%1], 16;" :: "r"(dst), "l"(src));
}
#define CP_COMMIT() asm volatile("cp.async.commit_group;" ::: "memory")

__device__ __forceinline__ void ldsm_x4(uint32_t* r, uint32_t addr) {
    asm volatile("ldmatrix.sync.aligned.m8n8.x4.shared.b16 {%0,%1,%2,%3}, [%4];"
                 : "=r"(r[0]), "=r"(r[1]), "=r"(r[2]), "=r"(r[3]) : "r"(addr));
}
__device__ __forceinline__ void mma16816(float* c, const uint32_t* a,
                                         uint32_t b0, uint32_t b1) {
    asm volatile(
        "mma.sync.aligned.m16n8k16.row.col.f32.f16.f16.f32 "
        "{%0,%1,%2,%3}, {%4,%5,%6,%7}, {%8,%9}, {%0,%1,%2,%3};"
        : "+f"(c[0]), "+f"(c[1]), "+f"(c[2]), "+f"(c[3])
        : "r"(a[0]), "r"(a[1]), "r"(a[2]), "r"(a[3]), "r"(b0), "r"(b1));
}
// 8 halves (uint4) -> 8 floats
__device__ __forceinline__ void h8_to_f8(uint4 u, float* f) {
    const __half2* h = reinterpret_cast<const __half2*>(&u);
    float2 t;
    t = __half22float2(h[0]); f[0] = t.x; f[1] = t.y;
    t = __half22float2(h[1]); f[2] = t.x; f[3] = t.y;
    t = __half22float2(h[2]); f[4] = t.x; f[5] = t.y;
    t = __half22float2(h[3]); f[6] = t.x; f[7] = t.y;
}

// ======================= conversion kernels =================================
// x [M, DD] fp32 -> fp16 [M, DD]
__global__ void __launch_bounds__(256) convert_Ah_kernel(
    const float* __restrict__ in, __half* __restrict__ out)
{
    int i = blockIdx.x * blockDim.x + threadIdx.x;
    if (i >= MTOK * DD / 4) return;
    float4 v = reinterpret_cast<const float4*>(in)[i];
    __half2 p0 = __halves2half2(__float2half_rn(v.x), __float2half_rn(v.y));
    __half2 p1 = __halves2half2(__float2half_rn(v.z), __float2half_rn(v.w));
    uint2 u;
    u.x = *reinterpret_cast<uint32_t*>(&p0);
    u.y = *reinterpret_cast<uint32_t*>(&p1);
    reinterpret_cast<uint2*>(out)[i] = u;
}

// W [K=DD, N=DD] fp32 -> T [N, DD] fp16 (transposed)
__global__ void __launch_bounds__(256) convert_Wh_kernel(
    const float* __restrict__ W, __half* __restrict__ T)
{
    __shared__ float t[32][33];
    int bx = blockIdx.x * 32, by = blockIdx.y * 32;
    int tx = threadIdx.x, ty = threadIdx.y;
    for (int j = ty; j < 32; j += 8)
        t[j][tx] = W[(size_t)(by + j) * DD + bx + tx];
    __syncthreads();
    for (int j = ty; j < 32; j += 8) {
        float v = t[tx][j];
        T[(size_t)(bx + j) * DD + by + tx] = __float2half_rn(v);
    }
}

__global__ void pack_bias_kernel(const float* __restrict__ bq,
                                 const float* __restrict__ bk,
                                 const float* __restrict__ bv,
                                 float* __restrict__ out)
{
    int i = blockIdx.x * blockDim.x + threadIdx.x;
    if (i >= NQKV) return;
    out[i] = (i < DD) ? bq[i] : (i < 2 * DD) ? bk[i - DD] : bv[i - 2 * DD];
}

// ======================= mma.sync GEMM ======================================
// CTA tile 128x128, 8 warps (4x2), warp tile 32x64, BK=64, 3 stages.
#define GBM 128
#define GBN 128
#define GBK 64
#define GSTAGES 3
#define APAD 8
#define SROW (GBK + APAD)                    // 72 fp16 = 144 B
#define TILE_BYTES (GBM * SROW * 2)          // 18432
#define STAGE_BYTES (2 * TILE_BYTES)         // 36864 (A + B)
#define GEMM_SMEM (GSTAGES * STAGE_BYTES)    // 110592
#define GNIT (DD / GBK)                      // 16

// Shared mainloop; epilogue differs by output type via template.
template <typename OutT>
__global__ void __launch_bounds__(256, 2) gemm_mma_kernel(
    const __half* __restrict__ A, const __half* __restrict__ B,
    const float* __restrict__ bias, OutT* __restrict__ C, int N)
{
    extern __shared__ __half sm[];
    const uint32_t sbase = smem_u32(sm);

    const int tid = threadIdx.x;
    const int lane = tid & 31;
    const int wid = tid >> 5;
    const int wm = wid & 3;          // 0..3 -> 32-row slice
    const int wn = wid >> 2;         // 0..1 -> 64-col slice
    const int bm = blockIdx.y * GBM;
    const int bn = blockIdx.x * GBN;

    float acc[2][8][4];
#pragma unroll
    for (int i = 0; i < 2; i++)
#pragma unroll
        for (int j = 0; j < 8; j++)
#pragma unroll
            for (int q = 0; q < 4; q++) acc[i][j][q] = 0.f;

    auto load_stage = [&](int it, int s) {
        const int kt = it * GBK;
        const uint32_t st = sbase + s * STAGE_BYTES;
#pragma unroll
        for (int i = 0; i < 4; i++) {
            int c = tid + 256 * i;
            int r = c >> 3, ch = c & 7;
            uint32_t off = (r * SROW + ch * 8) * 2;
            cp_async16(st + off,              A + (size_t)(bm + r) * DD + kt + ch * 8);
            cp_async16(st + TILE_BYTES + off, B + (size_t)(bn + r) * DD + kt + ch * 8);
        }
        CP_COMMIT();
    };

    load_stage(0, 0);
    load_stage(1, 1);

    const int a_row = wm * 32 + (lane & 15);
    const int a_kof = ((lane >> 4) & 1) * 8;
    const int b_row = wn * 64 + ((lane >> 4) & 1) * 8 + (lane & 7);
    const int b_kof = ((lane >> 3) & 1) * 8;

    uint32_t af[2][2][4], bf[2][4][4];

    auto load_frags = [&](int buf, uint32_t abase, uint32_t bbase, int k0) {
#pragma unroll
        for (int mi = 0; mi < 2; mi++)
            ldsm_x4(af[buf][mi], abase + ((a_row + mi * 16) * SROW + k0 + a_kof) * 2);
#pragma unroll
        for (int nj = 0; nj < 4; nj++)
            ldsm_x4(bf[buf][nj], bbase + ((b_row + nj * 16) * SROW + k0 + b_kof) * 2);
    };
    auto do_mmas = [&](int buf) {
#pragma unroll
        for (int mi = 0; mi < 2; mi++)
#pragma unroll
            for (int nj = 0; nj < 4; nj++) {
                mma16816(acc[mi][2 * nj],     af[buf][mi], bf[buf][nj][0], bf[buf][nj][1]);
                mma16816(acc[mi][2 * nj + 1], af[buf][mi], bf[buf][nj][2], bf[buf][nj][3]);
            }
    };

    for (int it = 0; it < GNIT; it++) {
        const int s = it % 3;
        asm volatile("cp.async.wait_group 1;" ::: "memory");
        __syncthreads();

        if (it + 2 < GNIT) load_stage(it + 2, (it + 2) % 3);
        else CP_COMMIT();

        const uint32_t abase = sbase + s * STAGE_BYTES;
        const uint32_t bbase = abase + TILE_BYTES;
        load_frags(0, abase, bbase, 0);
#pragma unroll
        for (int ks = 0; ks < 4; ks++) {
            if (ks < 3) load_frags((ks + 1) & 1, abase, bbase, (ks + 1) * 16);
            do_mmas(ks & 1);
        }
    }

    // epilogue (fp32 or fp16 output)
#pragma unroll
    for (int mi = 0; mi < 2; mi++) {
#pragma unroll
        for (int ni = 0; ni < 8; ni++) {
            int row = bm + wm * 32 + mi * 16 + (lane >> 2);
            int col = bn + wn * 64 + ni * 8 + (lane & 3) * 2;
            float b0 = __ldg(&bias[col]), b1 = __ldg(&bias[col + 1]);
            float c00 = acc[mi][ni][0] + b0, c01 = acc[mi][ni][1] + b1;
            float c10 = acc[mi][ni][2] + b0, c11 = acc[mi][ni][3] + b1;
            if constexpr (sizeof(OutT) == 4) {
                float2 v0 = {c00, c01}, v1 = {c10, c11};
                *reinterpret_cast<float2*>(&C[(size_t)row * N + col]) = v0;
                *reinterpret_cast<float2*>(&C[(size_t)(row + 8) * N + col]) = v1;
            } else {
                __half2 h0 = __floats2half2_rn(c00, c01);
                __half2 h1 = __floats2half2_rn(c10, c11);
                *reinterpret_cast<__half2*>(&C[(size_t)row * N + col]) = h0;
                *reinterpret_cast<__half2*>(&C[(size_t)(row + 8) * N + col]) = h1;
            }
        }
    }
}

// ======================= per-token attention ================================
// 2 tokens per 128-thread block. QKV row = fp16 [q(1024)|k(1024)|v(1024)].
// Scores/softmax/PV in fp32; output written as fp16 into Ah.
__global__ void __launch_bounds__(128) attn_kernel(
    const __half* __restrict__ QKV, __half* __restrict__ Ah)
{
    __shared__ __half sk[2][DD];   // 2 KB per token
    __shared__ __half sv[2][DD];

    const int tid = threadIdx.x;
    const int sub = tid >> 6;        // token within block
    const int i = tid & 63;          // my HD row
    const int t = blockIdx.x * 2 + sub;
    const __half* row = QKV + (size_t)t * NQKV;

    // stage k,v (1024 halves each = 128 uint4); 64 threads x 2
#pragma unroll
    for (int h = 0; h < 2; h++) {
        int idx = i + h * 64;
        reinterpret_cast<uint4*>(sk[sub])[idx] =
            reinterpret_cast<const uint4*>(row + DD)[idx];
        reinterpret_cast<uint4*>(sv[sub])[idx] =
            reinterpret_cast<const uint4*>(row + 2 * DD)[idx];
    }
    // q row -> fp32 regs
    float q[16];
    {
        uint4 u0 = reinterpret_cast<const uint4*>(row)[i * 2 + 0];
        uint4 u1 = reinterpret_cast<const uint4*>(row)[i * 2 + 1];
        h8_to_f8(u0, q);
        h8_to_f8(u1, q + 8);
    }
    __syncthreads();

    float s[HD];
    float mx = -INFINITY;
#pragma unroll 8
    for (int kk = 0; kk < HD; kk++) {
        float kf[16];
        uint4 u0 = reinterpret_cast<const uint4*>(sk[sub])[kk * 2 + 0];
        uint4 u1 = reinterpret_cast<const uint4*>(sk[sub])[kk * 2 + 1];
        h8_to_f8(u0, kf);
        h8_to_f8(u1, kf + 8);
        float dot = 0.f;
#pragma unroll
        for (int d = 0; d < 16; d++) dot = fmaf(q[d], kf[d], dot);
        float val = dot * 0.25f + 1e-6f;
        bool valid = (kk <= i) && (val != 0.0f);
        s[kk] = valid ? val : -INFINITY;
        if (valid) mx = fmaxf(mx, val);
    }

    float sum = 0.f;
#pragma unroll 8
    for (int kk = 0; kk < HD; kk++) {
        float e = (s[kk] == -INFINITY) ? 0.f : __expf(s[kk] - mx);
        s[kk] = e;
        sum += e;
    }
    float inv = 1.f / sum;

    float acc[16];
#pragma unroll
    for (int d = 0; d < 16; d++) acc[d] = 0.f;
#pragma unroll 8
    for (int kk = 0; kk < HD; kk++) {    // uniform: masked probs are exactly 0
        float p = s[kk] * inv;
        float vf[16];
        uint4 u0 = reinterpret_cast<const uint4*>(sv[sub])[kk * 2 + 0];
        uint4 u1 = reinterpret_cast<const uint4*>(sv[sub])[kk * 2 + 1];
        h8_to_f8(u0, vf);
        h8_to_f8(u1, vf + 8);
#pragma unroll
        for (int d = 0; d < 16; d++) acc[d] = fmaf(p, vf[d], acc[d]);
    }

    // fp16 store
    uint32_t hv[8];
#pragma unroll
    for (int j = 0; j < 8; j++) {
        __half2 ph = __floats2half2_rn(acc[2 * j], acc[2 * j + 1]);
        hv[j] = *reinterpret_cast<uint32_t*>(&ph);
    }
    __half* ob = Ah + (size_t)t * DD + i * NH;
    uint4* u = reinterpret_cast<uint4*>(hv);
    reinterpret_cast<uint4*>(ob)[0] = u[0];
    reinterpret_cast<uint4*>(ob)[1] = u[1];
}

// ======================= launch =============================================
extern "C" void kernel_launch(void* const* d_in, const int* in_sizes, int n_in,
                              void* d_out, int out_size)
{
    const float* x  = (const float*)d_in[0];
    const float* Wq = (const float*)d_in[1];
    const float* bq = (const float*)d_in[2];
    const float* Wk = (const float*)d_in[3];
    const float* bk = (const float*)d_in[4];
    const float* Wv = (const float*)d_in[5];
    const float* bv = (const float*)d_in[6];
    const float* Wo = (const float*)d_in[7];
    const float* bo = (const float*)d_in[8];
    float* out = (float*)d_out;

    float *bqkv;
    __half *QKVp, *Ah, *Wh;
    cudaGetSymbolAddress((void**)&QKVp, g_QKV);
    cudaGetSymbolAddress((void**)&Ah, g_Ah);
    cudaGetSymbolAddress((void**)&Wh, g_Wh);
    cudaGetSymbolAddress((void**)&bqkv, g_bqkv);

    cudaFuncSetAttribute(gemm_mma_kernel<__half>,
                         cudaFuncAttributeMaxDynamicSharedMemorySize, GEMM_SMEM);
    cudaFuncSetAttribute(gemm_mma_kernel<float>,
                         cudaFuncAttributeMaxDynamicSharedMemorySize, GEMM_SMEM);

    const int n4 = MTOK * DD / 4;
    dim3 cgrid((n4 + 255) / 256);
    dim3 wgrid(DD / 32, DD / 32), wblk(32, 8);

    pack_bias_kernel<<<(NQKV + 255) / 256, 256>>>(bq, bk, bv, bqkv);       // 0
    convert_Ah_kernel<<<cgrid, 256>>>(x, Ah);                              // 1
    convert_Wh_kernel<<<wgrid, wblk>>>(Wq, Wh + 0ULL * DD * DD);           // 2
    convert_Wh_kernel<<<wgrid, wblk>>>(Wk, Wh + 1ULL * DD * DD);           // 3
    convert_Wh_kernel<<<wgrid, wblk>>>(Wv, Wh + 2ULL * DD * DD);           // 4

    // fused QKV projection: fp16 out
    dim3 qkv_grid(NQKV / GBN, MTOK / GBM);   // (24, 128)
    gemm_mma_kernel<__half><<<qkv_grid, 256, GEMM_SMEM>>>(Ah, Wh, bqkv, QKVp, NQKV);  // 5

    attn_kernel<<<MTOK / 2, 128>>>(QKVp, Ah);                              // 6

    convert_Wh_kernel<<<wgrid, wblk>>>(Wo, Wh + 3ULL * DD * DD);           // 7

    // output projection: fp32 out
    dim3 o_grid(DD / GBN, MTOK / GBM);       // (8, 128)
    gemm_mma_kernel<float><<<o_grid, 256, GEMM_SMEM>>>(Ah, Wh + 3ULL * DD * DD, bo, out, DD);  // 8
}

// round 14
// speedup vs baseline: 1.0457x; 1.0457x over previous
#include <cuda_runtime.h>
#include <cuda_fp16.h>
#include <math.h>
#include <stdint.h>

// Problem shape (fixed)
#define BB 8
#define LL 2048
#define DD 1024
#define NH 16
#define HD 64
#define MTOK (BB * LL)        // 16384 tokens
#define NQKV (3 * DD)         // 3072: fused q|k|v output width

// ======================= scratch ============================================
__device__ __half g_QKV[(size_t)MTOK * NQKV];     // 96 MB fp16 (q|k|v per row)
__device__ __half g_Ah[(size_t)MTOK * DD];        // 32 MB fp16 activations
__device__ __half g_Wh[4ULL * DD * DD];           // 8 MB fp16 weights (transposed)
__device__ float  g_bqkv[NQKV];

// ======================= small helpers ======================================
__device__ __forceinline__ uint32_t smem_u32(const void* p) {
    uint32_t a;
    asm("{ .reg .u64 t; cvta.to.shared.u64 t, %1; cvt.u32.u64 %0, t; }"
        : "=r"(a) : "l"(p));
    return a;
}
__device__ __forceinline__ void cp_async16(uint32_t dst, const void* src) {
    asm volatile("cp.async.cg.shared.global [%0], [%1], 16;" :: "r"(dst), "l"(src));
}
#define CP_COMMIT() asm volatile("cp.async.commit_group;" ::: "memory")

__device__ __forceinline__ void ldsm_x4(uint32_t* r, uint32_t addr) {
    asm volatile("ldmatrix.sync.aligned.m8n8.x4.shared.b16 {%0,%1,%2,%3}, [%4];"
                 : "=r"(r[0]), "=r"(r[1]), "=r"(r[2]), "=r"(r[3]) : "r"(addr));
}
__device__ __forceinline__ void mma16816(float* c, const uint32_t* a,
                                         uint32_t b0, uint32_t b1) {
    asm volatile(
        "mma.sync.aligned.m16n8k16.row.col.f32.f16.f16.f32 "
        "{%0,%1,%2,%3}, {%4,%5,%6,%7}, {%8,%9}, {%0,%1,%2,%3};"
        : "+f"(c[0]), "+f"(c[1]), "+f"(c[2]), "+f"(c[3])
        : "r"(a[0]), "r"(a[1]), "r"(a[2]), "r"(a[3]), "r"(b0), "r"(b1));
}
// 8 halves (uint4) -> two float4
__device__ __forceinline__ void h8_to_2f4(uint4 u, float4& a, float4& b) {
    const __half2* h = reinterpret_cast<const __half2*>(&u);
    float2 t0 = __half22float2(h[0]);
    float2 t1 = __half22float2(h[1]);
    float2 t2 = __half22float2(h[2]);
    float2 t3 = __half22float2(h[3]);
    a = make_float4(t0.x, t0.y, t1.x, t1.y);
    b = make_float4(t2.x, t2.y, t3.x, t3.y);
}

// ======================= conversion kernels =================================
// x [M, DD] fp32 -> fp16 [M, DD]
__global__ void __launch_bounds__(256) convert_Ah_kernel(
    const float* __restrict__ in, __half* __restrict__ out)
{
    int i = blockIdx.x * blockDim.x + threadIdx.x;
    if (i >= MTOK * DD / 4) return;
    float4 v = reinterpret_cast<const float4*>(in)[i];
    __half2 p0 = __halves2half2(__float2half_rn(v.x), __float2half_rn(v.y));
    __half2 p1 = __halves2half2(__float2half_rn(v.z), __float2half_rn(v.w));
    uint2 u;
    u.x = *reinterpret_cast<uint32_t*>(&p0);
    u.y = *reinterpret_cast<uint32_t*>(&p1);
    reinterpret_cast<uint2*>(out)[i] = u;
}

// W [K=DD, N=DD] fp32 -> T [N, DD] fp16 (transposed)
__global__ void __launch_bounds__(256) convert_Wh_kernel(
    const float* __restrict__ W, __half* __restrict__ T)
{
    __shared__ float t[32][33];
    int bx = blockIdx.x * 32, by = blockIdx.y * 32;
    int tx = threadIdx.x, ty = threadIdx.y;
    for (int j = ty; j < 32; j += 8)
        t[j][tx] = W[(size_t)(by + j) * DD + bx + tx];
    __syncthreads();
    for (int j = ty; j < 32; j += 8) {
        float v = t[tx][j];
        T[(size_t)(bx + j) * DD + by + tx] = __float2half_rn(v);
    }
}

__global__ void pack_bias_kernel(const float* __restrict__ bq,
                                 const float* __restrict__ bk,
                                 const float* __restrict__ bv,
                                 float* __restrict__ out)
{
    int i = blockIdx.x * blockDim.x + threadIdx.x;
    if (i >= NQKV) return;
    out[i] = (i < DD) ? bq[i] : (i < 2 * DD) ? bk[i - DD] : bv[i - 2 * DD];
}

// ======================= mma.sync GEMM ======================================
// CTA tile 128x128, 8 warps (4x2), warp tile 32x64, BK=64, 3 stages.
#define GBM 128
#define GBN 128
#define GBK 64
#define GSTAGES 3
#define APAD 8
#define SROW (GBK + APAD)                    // 72 fp16 = 144 B
#define TILE_BYTES (GBM * SROW * 2)          // 18432
#define STAGE_BYTES (2 * TILE_BYTES)         // 36864 (A + B)
#define GEMM_SMEM (GSTAGES * STAGE_BYTES)    // 110592
#define GNIT (DD / GBK)                      // 16

// Shared mainloop; epilogue differs by output type via template.
template <typename OutT>
__global__ void __launch_bounds__(256, 2) gemm_mma_kernel(
    const __half* __restrict__ A, const __half* __restrict__ B,
    const float* __restrict__ bias, OutT* __restrict__ C, int N)
{
    extern __shared__ __half sm[];
    const uint32_t sbase = smem_u32(sm);

    const int tid = threadIdx.x;
    const int lane = tid & 31;
    const int wid = tid >> 5;
    const int wm = wid & 3;          // 0..3 -> 32-row slice
    const int wn = wid >> 2;         // 0..1 -> 64-col slice
    const int bm = blockIdx.y * GBM;
    const int bn = blockIdx.x * GBN;

    float acc[2][8][4];
#pragma unroll
    for (int i = 0; i < 2; i++)
#pragma unroll
        for (int j = 0; j < 8; j++)
#pragma unroll
            for (int q = 0; q < 4; q++) acc[i][j][q] = 0.f;

    auto load_stage = [&](int it, int s) {
        const int kt = it * GBK;
        const uint32_t st = sbase + s * STAGE_BYTES;
#pragma unroll
        for (int i = 0; i < 4; i++) {
            int c = tid + 256 * i;
            int r = c >> 3, ch = c & 7;
            uint32_t off = (r * SROW + ch * 8) * 2;
            cp_async16(st + off,              A + (size_t)(bm + r) * DD + kt + ch * 8);
            cp_async16(st + TILE_BYTES + off, B + (size_t)(bn + r) * DD + kt + ch * 8);
        }
        CP_COMMIT();
    };

    load_stage(0, 0);
    load_stage(1, 1);

    const int a_row = wm * 32 + (lane & 15);
    const int a_kof = ((lane >> 4) & 1) * 8;
    const int b_row = wn * 64 + ((lane >> 4) & 1) * 8 + (lane & 7);
    const int b_kof = ((lane >> 3) & 1) * 8;

    uint32_t af[2][2][4], bf[2][4][4];

    auto load_frags = [&](int buf, uint32_t abase, uint32_t bbase, int k0) {
#pragma unroll
        for (int mi = 0; mi < 2; mi++)
            ldsm_x4(af[buf][mi], abase + ((a_row + mi * 16) * SROW + k0 + a_kof) * 2);
#pragma unroll
        for (int nj = 0; nj < 4; nj++)
            ldsm_x4(bf[buf][nj], bbase + ((b_row + nj * 16) * SROW + k0 + b_kof) * 2);
    };
    auto do_mmas = [&](int buf) {
#pragma unroll
        for (int mi = 0; mi < 2; mi++)
#pragma unroll
            for (int nj = 0; nj < 4; nj++) {
                mma16816(acc[mi][2 * nj],     af[buf][mi], bf[buf][nj][0], bf[buf][nj][1]);
                mma16816(acc[mi][2 * nj + 1], af[buf][mi], bf[buf][nj][2], bf[buf][nj][3]);
            }
    };

    for (int it = 0; it < GNIT; it++) {
        const int s = it % 3;
        asm volatile("cp.async.wait_group 1;" ::: "memory");
        __syncthreads();

        if (it + 2 < GNIT) load_stage(it + 2, (it + 2) % 3);
        else CP_COMMIT();

        const uint32_t abase = sbase + s * STAGE_BYTES;
        const uint32_t bbase = abase + TILE_BYTES;
        load_frags(0, abase, bbase, 0);
#pragma unroll
        for (int ks = 0; ks < 4; ks++) {
            if (ks < 3) load_frags((ks + 1) & 1, abase, bbase, (ks + 1) * 16);
            do_mmas(ks & 1);
        }
    }

    // epilogue (fp32 or fp16 output)
#pragma unroll
    for (int mi = 0; mi < 2; mi++) {
#pragma unroll
        for (int ni = 0; ni < 8; ni++) {
            int row = bm + wm * 32 + mi * 16 + (lane >> 2);
            int col = bn + wn * 64 + ni * 8 + (lane & 3) * 2;
            float b0 = __ldg(&bias[col]), b1 = __ldg(&bias[col + 1]);
            float c00 = acc[mi][ni][0] + b0, c01 = acc[mi][ni][1] + b1;
            float c10 = acc[mi][ni][2] + b0, c11 = acc[mi][ni][3] + b1;
            if constexpr (sizeof(OutT) == 4) {
                float2 v0 = {c00, c01}, v1 = {c10, c11};
                *reinterpret_cast<float2*>(&C[(size_t)row * N + col]) = v0;
                *reinterpret_cast<float2*>(&C[(size_t)(row + 8) * N + col]) = v1;
            } else {
                __half2 h0 = __floats2half2_rn(c00, c01);
                __half2 h1 = __floats2half2_rn(c10, c11);
                *reinterpret_cast<__half2*>(&C[(size_t)row * N + col]) = h0;
                *reinterpret_cast<__half2*>(&C[(size_t)(row + 8) * N + col]) = h1;
            }
        }
    }
}

// ======================= per-token attention ================================
// 2 tokens per 128-thread block. QKV row = fp16 [q|k|v]; k,v converted to fp32
// ONCE during smem staging; inner loops are pure fp32 (R12 profile).
__global__ void __launch_bounds__(128) attn_kernel(
    const __half* __restrict__ QKV, __half* __restrict__ Ah)
{
    __shared__ float sk[2][DD];
    __shared__ float sv[2][DD];

    const int tid = threadIdx.x;
    const int sub = tid >> 6;        // token within block
    const int i = tid & 63;          // my HD row
    const int t = blockIdx.x * 2 + sub;
    const __half* row = QKV + (size_t)t * NQKV;

    // stage k,v with one-time fp16->fp32 conversion (128 uint4 each, 2/thread)
#pragma unroll
    for (int h = 0; h < 2; h++) {
        int idx = i + h * 64;        // uint4 slot 0..127 (8 halves each)
        float4 a, b;
        uint4 uk = reinterpret_cast<const uint4*>(row + DD)[idx];
        h8_to_2f4(uk, a, b);
        reinterpret_cast<float4*>(sk[sub])[idx * 2 + 0] = a;
        reinterpret_cast<float4*>(sk[sub])[idx * 2 + 1] = b;
        uint4 uv = reinterpret_cast<const uint4*>(row + 2 * DD)[idx];
        h8_to_2f4(uv, a, b);
        reinterpret_cast<float4*>(sv[sub])[idx * 2 + 0] = a;
        reinterpret_cast<float4*>(sv[sub])[idx * 2 + 1] = b;
    }
    // q row -> fp32 regs (converted once)
    float4 q0, q1, q2, q3;
    {
        uint4 u0 = reinterpret_cast<const uint4*>(row)[i * 2 + 0];
        uint4 u1 = reinterpret_cast<const uint4*>(row)[i * 2 + 1];
        h8_to_2f4(u0, q0, q1);
        h8_to_2f4(u1, q2, q3);
    }
    __syncthreads();

    float s[HD];
    float mx = -INFINITY;
#pragma unroll 8
    for (int kk = 0; kk < HD; kk++) {
        float4 k0 = reinterpret_cast<const float4*>(sk[sub])[kk * 4 + 0];
        float4 k1 = reinterpret_cast<const float4*>(sk[sub])[kk * 4 + 1];
        float4 k2 = reinterpret_cast<const float4*>(sk[sub])[kk * 4 + 2];
        float4 k3 = reinterpret_cast<const float4*>(sk[sub])[kk * 4 + 3];
        float dot = q0.x * k0.x + q0.y * k0.y + q0.z * k0.z + q0.w * k0.w
                  + q1.x * k1.x + q1.y * k1.y + q1.z * k1.z + q1.w * k1.w
                  + q2.x * k2.x + q2.y * k2.y + q2.z * k2.z + q2.w * k2.w
                  + q3.x * k3.x + q3.y * k3.y + q3.z * k3.z + q3.w * k3.w;
        float val = dot * 0.25f + 1e-6f;
        bool valid = (kk <= i) && (val != 0.0f);
        s[kk] = valid ? val : -INFINITY;
        if (valid) mx = fmaxf(mx, val);
    }

    float sum = 0.f;
#pragma unroll 8
    for (int kk = 0; kk < HD; kk++) {
        float e = (s[kk] == -INFINITY) ? 0.f : __expf(s[kk] - mx);
        s[kk] = e;
        sum += e;
    }
    float inv = 1.f / sum;

    float4 acc0 = {0, 0, 0, 0}, acc1 = {0, 0, 0, 0};
    float4 acc2 = {0, 0, 0, 0}, acc3 = {0, 0, 0, 0};
#pragma unroll 8
    for (int kk = 0; kk < HD; kk++) {    // uniform: masked probs are exactly 0
        float p = s[kk] * inv;
        float4 v0 = reinterpret_cast<const float4*>(sv[sub])[kk * 4 + 0];
        float4 v1 = reinterpret_cast<const float4*>(sv[sub])[kk * 4 + 1];
        float4 v2 = reinterpret_cast<const float4*>(sv[sub])[kk * 4 + 2];
        float4 v3 = reinterpret_cast<const float4*>(sv[sub])[kk * 4 + 3];
        acc0.x = fmaf(p, v0.x, acc0.x); acc0.y = fmaf(p, v0.y, acc0.y);
        acc0.z = fmaf(p, v0.z, acc0.z); acc0.w = fmaf(p, v0.w, acc0.w);
        acc1.x = fmaf(p, v1.x, acc1.x); acc1.y = fmaf(p, v1.y, acc1.y);
        acc1.z = fmaf(p, v1.z, acc1.z); acc1.w = fmaf(p, v1.w, acc1.w);
        acc2.x = fmaf(p, v2.x, acc2.x); acc2.y = fmaf(p, v2.y, acc2.y);
        acc2.z = fmaf(p, v2.z, acc2.z); acc2.w = fmaf(p, v2.w, acc2.w);
        acc3.x = fmaf(p, v3.x, acc3.x); acc3.y = fmaf(p, v3.y, acc3.y);
        acc3.z = fmaf(p, v3.z, acc3.z); acc3.w = fmaf(p, v3.w, acc3.w);
    }

    // fp16 store
    float a[16] = {acc0.x, acc0.y, acc0.z, acc0.w, acc1.x, acc1.y, acc1.z, acc1.w,
                   acc2.x, acc2.y, acc2.z, acc2.w, acc3.x, acc3.y, acc3.z, acc3.w};
    uint32_t hv[8];
#pragma unroll
    for (int j = 0; j < 8; j++) {
        __half2 ph = __floats2half2_rn(a[2 * j], a[2 * j + 1]);
        hv[j] = *reinterpret_cast<uint32_t*>(&ph);
    }
    __half* ob = Ah + (size_t)t * DD + i * NH;
    uint4* u = reinterpret_cast<uint4*>(hv);
    reinterpret_cast<uint4*>(ob)[0] = u[0];
    reinterpret_cast<uint4*>(ob)[1] = u[1];
}

// ======================= launch =============================================
extern "C" void kernel_launch(void* const* d_in, const int* in_sizes, int n_in,
                              void* d_out, int out_size)
{
    const float* x  = (const float*)d_in[0];
    const float* Wq = (const float*)d_in[1];
    const float* bq = (const float*)d_in[2];
    const float* Wk = (const float*)d_in[3];
    const float* bk = (const float*)d_in[4];
    const float* Wv = (const float*)d_in[5];
    const float* bv = (const float*)d_in[6];
    const float* Wo = (const float*)d_in[7];
    const float* bo = (const float*)d_in[8];
    float* out = (float*)d_out;

    float *bqkv;
    __half *QKVp, *Ah, *Wh;
    cudaGetSymbolAddress((void**)&QKVp, g_QKV);
    cudaGetSymbolAddress((void**)&Ah, g_Ah);
    cudaGetSymbolAddress((void**)&Wh, g_Wh);
    cudaGetSymbolAddress((void**)&bqkv, g_bqkv);

    cudaFuncSetAttribute(gemm_mma_kernel<__half>,
                         cudaFuncAttributeMaxDynamicSharedMemorySize, GEMM_SMEM);
    cudaFuncSetAttribute(gemm_mma_kernel<float>,
                         cudaFuncAttributeMaxDynamicSharedMemorySize, GEMM_SMEM);

    const int n4 = MTOK * DD / 4;
    dim3 cgrid((n4 + 255) / 256);
    dim3 wgrid(DD / 32, DD / 32), wblk(32, 8);

    pack_bias_kernel<<<(NQKV + 255) / 256, 256>>>(bq, bk, bv, bqkv);       // 0
    convert_Ah_kernel<<<cgrid, 256>>>(x, Ah);                              // 1
    convert_Wh_kernel<<<wgrid, wblk>>>(Wq, Wh + 0ULL * DD * DD);           // 2
    convert_Wh_kernel<<<wgrid, wblk>>>(Wk, Wh + 1ULL * DD * DD);           // 3
    convert_Wh_kernel<<<wgrid, wblk>>>(Wv, Wh + 2ULL * DD * DD);           // 4

    // fused QKV projection: fp16 out
    dim3 qkv_grid(NQKV / GBN, MTOK / GBM);   // (24, 128)
    gemm_mma_kernel<__half><<<qkv_grid, 256, GEMM_SMEM>>>(Ah, Wh, bqkv, QKVp, NQKV);  // 5

    attn_kernel<<<MTOK / 2, 128>>>(QKVp, Ah);                              // 6

    convert_Wh_kernel<<<wgrid, wblk>>>(Wo, Wh + 3ULL * DD * DD);           // 7

    // output projection: fp32 out
    dim3 o_grid(DD / GBN, MTOK / GBM);       // (8, 128)
    gemm_mma_kernel<float><<<o_grid, 256, GEMM_SMEM>>>(Ah, Wh + 3ULL * DD * DD, bo, out, DD);  // 8
}

// round 15
// speedup vs baseline: 1.2503x; 1.1956x over previous
#include <cuda_runtime.h>
#include <cuda_fp16.h>
#include <math.h>
#include <stdint.h>

// Problem shape (fixed)
#define BB 8
#define LL 2048
#define DD 1024
#define NH 16
#define HD 64
#define MTOK (BB * LL)        // 16384 tokens
#define NQKV (3 * DD)         // 3072: fused q|k|v output width

// ======================= scratch ============================================
__device__ __half g_QKV[(size_t)MTOK * NQKV];     // 96 MB fp16 (q|k|v per row)
__device__ __half g_Ah[(size_t)MTOK * DD];        // 32 MB fp16 activations
__device__ __half g_Wh[4ULL * DD * DD];           // 8 MB fp16 weights (transposed)
__device__ float  g_bqkv[NQKV];

// ======================= small helpers ======================================
__device__ __forceinline__ uint32_t smem_u32(const void* p) {
    uint32_t a;
    asm("{ .reg .u64 t; cvta.to.shared.u64 t, %1; cvt.u32.u64 %0, t; }"
        : "=r"(a) : "l"(p));
    return a;
}
__device__ __forceinline__ void cp_async16(uint32_t dst, const void* src) {
    asm volatile("cp.async.cg.shared.global [%0], [%1], 16;" :: "r"(dst), "l"(src));
}
#define CP_COMMIT() asm volatile("cp.async.commit_group;" ::: "memory")

__device__ __forceinline__ void ldsm_x4(uint32_t* r, uint32_t addr) {
    asm volatile("ldmatrix.sync.aligned.m8n8.x4.shared.b16 {%0,%1,%2,%3}, [%4];"
                 : "=r"(r[0]), "=r"(r[1]), "=r"(r[2]), "=r"(r[3]) : "r"(addr));
}
__device__ __forceinline__ void ldsm_x4_trans(uint32_t* r, uint32_t addr) {
    asm volatile("ldmatrix.sync.aligned.m8n8.x4.trans.shared.b16 {%0,%1,%2,%3}, [%4];"
                 : "=r"(r[0]), "=r"(r[1]), "=r"(r[2]), "=r"(r[3]) : "r"(addr));
}
__device__ __forceinline__ void mma16816(float* c, const uint32_t* a,
                                         uint32_t b0, uint32_t b1) {
    asm volatile(
        "mma.sync.aligned.m16n8k16.row.col.f32.f16.f16.f32 "
        "{%0,%1,%2,%3}, {%4,%5,%6,%7}, {%8,%9}, {%0,%1,%2,%3};"
        : "+f"(c[0]), "+f"(c[1]), "+f"(c[2]), "+f"(c[3])
        : "r"(a[0]), "r"(a[1]), "r"(a[2]), "r"(a[3]), "r"(b0), "r"(b1));
}

// ======================= conversion kernels =================================
__global__ void __launch_bounds__(256) convert_Ah_kernel(
    const float* __restrict__ in, __half* __restrict__ out)
{
    int i = blockIdx.x * blockDim.x + threadIdx.x;
    if (i >= MTOK * DD / 4) return;
    float4 v = reinterpret_cast<const float4*>(in)[i];
    __half2 p0 = __halves2half2(__float2half_rn(v.x), __float2half_rn(v.y));
    __half2 p1 = __halves2half2(__float2half_rn(v.z), __float2half_rn(v.w));
    uint2 u;
    u.x = *reinterpret_cast<uint32_t*>(&p0);
    u.y = *reinterpret_cast<uint32_t*>(&p1);
    reinterpret_cast<uint2*>(out)[i] = u;
}

__global__ void __launch_bounds__(256) convert_Wh_kernel(
    const float* __restrict__ W, __half* __restrict__ T)
{
    __shared__ float t[32][33];
    int bx = blockIdx.x * 32, by = blockIdx.y * 32;
    int tx = threadIdx.x, ty = threadIdx.y;
    for (int j = ty; j < 32; j += 8)
        t[j][tx] = W[(size_t)(by + j) * DD + bx + tx];
    __syncthreads();
    for (int j = ty; j < 32; j += 8) {
        float v = t[tx][j];
        T[(size_t)(bx + j) * DD + by + tx] = __float2half_rn(v);
    }
}

__global__ void pack_bias_kernel(const float* __restrict__ bq,
                                 const float* __restrict__ bk,
                                 const float* __restrict__ bv,
                                 float* __restrict__ out)
{
    int i = blockIdx.x * blockDim.x + threadIdx.x;
    if (i >= NQKV) return;
    out[i] = (i < DD) ? bq[i] : (i < 2 * DD) ? bk[i - DD] : bv[i - 2 * DD];
}

// ======================= mma.sync GEMM ======================================
#define GBM 128
#define GBN 128
#define GBK 64
#define GSTAGES 3
#define APAD 8
#define SROW (GBK + APAD)                    // 72 fp16 = 144 B
#define TILE_BYTES (GBM * SROW * 2)          // 18432
#define STAGE_BYTES (2 * TILE_BYTES)         // 36864 (A + B)
#define GEMM_SMEM (GSTAGES * STAGE_BYTES)    // 110592
#define GNIT (DD / GBK)                      // 16

template <typename OutT>
__global__ void __launch_bounds__(256, 2) gemm_mma_kernel(
    const __half* __restrict__ A, const __half* __restrict__ B,
    const float* __restrict__ bias, OutT* __restrict__ C, int N)
{
    extern __shared__ __half sm[];
    const uint32_t sbase = smem_u32(sm);

    const int tid = threadIdx.x;
    const int lane = tid & 31;
    const int wid = tid >> 5;
    const int wm = wid & 3;
    const int wn = wid >> 2;
    const int bm = blockIdx.y * GBM;
    const int bn = blockIdx.x * GBN;

    float acc[2][8][4];
#pragma unroll
    for (int i = 0; i < 2; i++)
#pragma unroll
        for (int j = 0; j < 8; j++)
#pragma unroll
            for (int q = 0; q < 4; q++) acc[i][j][q] = 0.f;

    auto load_stage = [&](int it, int s) {
        const int kt = it * GBK;
        const uint32_t st = sbase + s * STAGE_BYTES;
#pragma unroll
        for (int i = 0; i < 4; i++) {
            int c = tid + 256 * i;
            int r = c >> 3, ch = c & 7;
            uint32_t off = (r * SROW + ch * 8) * 2;
            cp_async16(st + off,              A + (size_t)(bm + r) * DD + kt + ch * 8);
            cp_async16(st + TILE_BYTES + off, B + (size_t)(bn + r) * DD + kt + ch * 8);
        }
        CP_COMMIT();
    };

    load_stage(0, 0);
    load_stage(1, 1);

    const int a_row = wm * 32 + (lane & 15);
    const int a_kof = ((lane >> 4) & 1) * 8;
    const int b_row = wn * 64 + ((lane >> 4) & 1) * 8 + (lane & 7);
    const int b_kof = ((lane >> 3) & 1) * 8;

    uint32_t af[2][2][4], bf[2][4][4];

    auto load_frags = [&](int buf, uint32_t abase, uint32_t bbase, int k0) {
#pragma unroll
        for (int mi = 0; mi < 2; mi++)
            ldsm_x4(af[buf][mi], abase + ((a_row + mi * 16) * SROW + k0 + a_kof) * 2);
#pragma unroll
        for (int nj = 0; nj < 4; nj++)
            ldsm_x4(bf[buf][nj], bbase + ((b_row + nj * 16) * SROW + k0 + b_kof) * 2);
    };
    auto do_mmas = [&](int buf) {
#pragma unroll
        for (int mi = 0; mi < 2; mi++)
#pragma unroll
            for (int nj = 0; nj < 4; nj++) {
                mma16816(acc[mi][2 * nj],     af[buf][mi], bf[buf][nj][0], bf[buf][nj][1]);
                mma16816(acc[mi][2 * nj + 1], af[buf][mi], bf[buf][nj][2], bf[buf][nj][3]);
            }
    };

    for (int it = 0; it < GNIT; it++) {
        const int s = it % 3;
        asm volatile("cp.async.wait_group 1;" ::: "memory");
        __syncthreads();

        if (it + 2 < GNIT) load_stage(it + 2, (it + 2) % 3);
        else CP_COMMIT();

        const uint32_t abase = sbase + s * STAGE_BYTES;
        const uint32_t bbase = abase + TILE_BYTES;
        load_frags(0, abase, bbase, 0);
#pragma unroll
        for (int ks = 0; ks < 4; ks++) {
            if (ks < 3) load_frags((ks + 1) & 1, abase, bbase, (ks + 1) * 16);
            do_mmas(ks & 1);
        }
    }

#pragma unroll
    for (int mi = 0; mi < 2; mi++) {
#pragma unroll
        for (int ni = 0; ni < 8; ni++) {
            int row = bm + wm * 32 + mi * 16 + (lane >> 2);
            int col = bn + wn * 64 + ni * 8 + (lane & 3) * 2;
            float b0 = __ldg(&bias[col]), b1 = __ldg(&bias[col + 1]);
            float c00 = acc[mi][ni][0] + b0, c01 = acc[mi][ni][1] + b1;
            float c10 = acc[mi][ni][2] + b0, c11 = acc[mi][ni][3] + b1;
            if constexpr (sizeof(OutT) == 4) {
                float2 v0 = {c00, c01}, v1 = {c10, c11};
                *reinterpret_cast<float2*>(&C[(size_t)row * N + col]) = v0;
                *reinterpret_cast<float2*>(&C[(size_t)(row + 8) * N + col]) = v1;
            } else {
                __half2 h0 = __floats2half2_rn(c00, c01);
                __half2 h1 = __floats2half2_rn(c10, c11);
                *reinterpret_cast<__half2*>(&C[(size_t)row * N + col]) = h0;
                *reinterpret_cast<__half2*>(&C[(size_t)(row + 8) * N + col]) = h1;
            }
        }
    }
}

// ======================= tensor-core attention ==============================
// 2 tokens per 128-thread block; 2 warps per token (row halves 0-31 / 32-63).
// S = q@k^T via mma (fp16 in, fp32 acc), mask+softmax on fragments,
// P normalized in fp32, packed fp16, PV via mma with ldmatrix.trans V.
#define SROW2 24                       // 16 halves + 8 pad
#define TTILE (64 * SROW2)             // 1536 halves per padded 64x16 tile

__global__ void __launch_bounds__(128) attn_kernel(
    const __half* __restrict__ QKV, __half* __restrict__ Ah)
{
    __shared__ __half sm2[2 * 3 * TTILE];   // 2 tokens x {q,k,v}, 18432 B

    const int tid = threadIdx.x;
    const int lane = tid & 31;
    const int wid = tid >> 5;          // 0..3
    const int tokL = wid >> 1;         // token within block
    const int hm = wid & 1;            // row half (0: rows 0-31, 1: 32-63)
    const int t0 = blockIdx.x * 2;

    // stage 2 tokens x 3 mats x 128 uint4 chunks (16B each)
    for (int c = tid; c < 768; c += 128) {
        int tk = c / 384;
        int rem = c - tk * 384;
        int mat = rem >> 7;
        int ch = rem & 127;
        int row = ch >> 1, part = ch & 1;
        uint4 v = *reinterpret_cast<const uint4*>(
            QKV + (size_t)(t0 + tk) * NQKV + mat * DD + row * 16 + part * 8);
        *reinterpret_cast<uint4*>(
            &sm2[tk * 3 * TTILE + mat * TTILE + row * SROW2 + part * 8]) = v;
    }
    __syncthreads();

    const uint32_t qb = smem_u32(&sm2[tokL * 3 * TTILE]);
    const uint32_t kb = qb + TTILE * 2;
    const uint32_t vb = qb + 2 * TTILE * 2;

    // ---- S = q @ k^T  (rows hm*32..+31, all 64 keys) ----
    uint32_t aq[2][4];
#pragma unroll
    for (int mi = 0; mi < 2; mi++) {
        int r = hm * 32 + mi * 16 + (lane & 15);
        ldsm_x4(aq[mi], qb + (r * SROW2 + ((lane >> 4) & 1) * 8) * 2);
    }
    uint32_t bk[4][4];
#pragma unroll
    for (int nj = 0; nj < 4; nj++) {
        int r = nj * 16 + ((lane >> 4) & 1) * 8 + (lane & 7);
        ldsm_x4(bk[nj], kb + (r * SROW2 + ((lane >> 3) & 1) * 8) * 2);
    }
    float acc[2][8][4];
#pragma unroll
    for (int mi = 0; mi < 2; mi++)
#pragma unroll
        for (int ni = 0; ni < 8; ni++)
#pragma unroll
            for (int q = 0; q < 4; q++) acc[mi][ni][q] = 0.f;
#pragma unroll
    for (int mi = 0; mi < 2; mi++)
#pragma unroll
        for (int nj = 0; nj < 4; nj++) {
            mma16816(acc[mi][2 * nj],     aq[mi], bk[nj][0], bk[nj][1]);
            mma16816(acc[mi][2 * nj + 1], aq[mi], bk[nj][2], bk[nj][3]);
        }

    // ---- V fragments (trans): B col-major k16n8 from [key][dim] ----
    uint32_t bv[4][4];
#pragma unroll
    for (int kt = 0; kt < 4; kt++) {
        int r = kt * 16 + ((lane >> 3) & 1) * 8 + (lane & 7);
        ldsm_x4_trans(bv[kt], vb + (r * SROW2 + ((lane >> 4) & 1) * 8) * 2);
    }

    // ---- mask + softmax + P(fp16) + PV per m-tile ----
    float accO[2][2][4];
#pragma unroll
    for (int mi = 0; mi < 2; mi++)
#pragma unroll
        for (int nt = 0; nt < 2; nt++)
#pragma unroll
            for (int q = 0; q < 4; q++) accO[mi][nt][q] = 0.f;

    const int rlo = hm * 32 + (lane >> 2);   // +mi*16 later; r+8 for q2/q3
    const int cbase = (lane & 3) * 2;

#pragma unroll
    for (int mi = 0; mi < 2; mi++) {
        int r0 = rlo + mi * 16;
        int r1 = r0 + 8;
        float mx0 = -INFINITY, mx1 = -INFINITY;
#pragma unroll
        for (int ni = 0; ni < 8; ni++) {
            int j0 = ni * 8 + cbase, j1 = j0 + 1;
            float v0 = acc[mi][ni][0] * 0.25f + 1e-6f;
            float v1 = acc[mi][ni][1] * 0.25f + 1e-6f;
            float v2 = acc[mi][ni][2] * 0.25f + 1e-6f;
            float v3 = acc[mi][ni][3] * 0.25f + 1e-6f;
            acc[mi][ni][0] = (j0 <= r0 && v0 != 0.f) ? v0 : -INFINITY;
            acc[mi][ni][1] = (j1 <= r0 && v1 != 0.f) ? v1 : -INFINITY;
            acc[mi][ni][2] = (j0 <= r1 && v2 != 0.f) ? v2 : -INFINITY;
            acc[mi][ni][3] = (j1 <= r1 && v3 != 0.f) ? v3 : -INFINITY;
            mx0 = fmaxf(mx0, fmaxf(acc[mi][ni][0], acc[mi][ni][1]));
            mx1 = fmaxf(mx1, fmaxf(acc[mi][ni][2], acc[mi][ni][3]));
        }
        mx0 = fmaxf(mx0, __shfl_xor_sync(0xFFFFFFFF, mx0, 1));
        mx0 = fmaxf(mx0, __shfl_xor_sync(0xFFFFFFFF, mx0, 2));
        mx1 = fmaxf(mx1, __shfl_xor_sync(0xFFFFFFFF, mx1, 1));
        mx1 = fmaxf(mx1, __shfl_xor_sync(0xFFFFFFFF, mx1, 2));

        float s0 = 0.f, s1 = 0.f;
#pragma unroll
        for (int ni = 0; ni < 8; ni++) {
            float e0 = __expf(acc[mi][ni][0] - mx0);
            float e1 = __expf(acc[mi][ni][1] - mx0);
            float e2 = __expf(acc[mi][ni][2] - mx1);
            float e3 = __expf(acc[mi][ni][3] - mx1);
            acc[mi][ni][0] = e0; acc[mi][ni][1] = e1;
            acc[mi][ni][2] = e2; acc[mi][ni][3] = e3;
            s0 += e0 + e1; s1 += e2 + e3;
        }
        s0 += __shfl_xor_sync(0xFFFFFFFF, s0, 1);
        s0 += __shfl_xor_sync(0xFFFFFFFF, s0, 2);
        s1 += __shfl_xor_sync(0xFFFFFFFF, s1, 1);
        s1 += __shfl_xor_sync(0xFFFFFFFF, s1, 2);
        float inv0 = 1.f / s0, inv1 = 1.f / s1;

        // P -> fp16 A-fragments (acc n8-tile pair -> k16 A frag), then PV
#pragma unroll
        for (int kt = 0; kt < 4; kt++) {
            uint32_t aP[4];
            __half2 h;
            h = __floats2half2_rn(acc[mi][2 * kt][0] * inv0, acc[mi][2 * kt][1] * inv0);
            aP[0] = *reinterpret_cast<uint32_t*>(&h);
            h = __floats2half2_rn(acc[mi][2 * kt][2] * inv1, acc[mi][2 * kt][3] * inv1);
            aP[1] = *reinterpret_cast<uint32_t*>(&h);
            h = __floats2half2_rn(acc[mi][2 * kt + 1][0] * inv0, acc[mi][2 * kt + 1][1] * inv0);
            aP[2] = *reinterpret_cast<uint32_t*>(&h);
            h = __floats2half2_rn(acc[mi][2 * kt + 1][2] * inv1, acc[mi][2 * kt + 1][3] * inv1);
            aP[3] = *reinterpret_cast<uint32_t*>(&h);
#pragma unroll
            for (int nt = 0; nt < 2; nt++)
                mma16816(accO[mi][nt], aP, bv[kt][nt * 2], bv[kt][nt * 2 + 1]);
        }
    }

    // ---- store O (fp16) into Ah: row i dims 16 at [t*DD + i*16 + d] ----
    __half* ob = Ah + (size_t)(t0 + tokL) * DD;
#pragma unroll
    for (int mi = 0; mi < 2; mi++) {
        int r0 = rlo + mi * 16;
#pragma unroll
        for (int nt = 0; nt < 2; nt++) {
            int col = nt * 8 + cbase;
            __half2 h0 = __floats2half2_rn(accO[mi][nt][0], accO[mi][nt][1]);
            __half2 h1 = __floats2half2_rn(accO[mi][nt][2], accO[mi][nt][3]);
            *reinterpret_cast<__half2*>(ob + r0 * 16 + col) = h0;
            *reinterpret_cast<__half2*>(ob + (r0 + 8) * 16 + col) = h1;
        }
    }
}

// ======================= launch =============================================
extern "C" void kernel_launch(void* const* d_in, const int* in_sizes, int n_in,
                              void* d_out, int out_size)
{
    const float* x  = (const float*)d_in[0];
    const float* Wq = (const float*)d_in[1];
    const float* bq = (const float*)d_in[2];
    const float* Wk = (const float*)d_in[3];
    const float* bk = (const float*)d_in[4];
    const float* Wv = (const float*)d_in[5];
    const float* bv = (const float*)d_in[6];
    const float* Wo = (const float*)d_in[7];
    const float* bo = (const float*)d_in[8];
    float* out = (float*)d_out;

    float *bqkv;
    __half *QKVp, *Ah, *Wh;
    cudaGetSymbolAddress((void**)&QKVp, g_QKV);
    cudaGetSymbolAddress((void**)&Ah, g_Ah);
    cudaGetSymbolAddress((void**)&Wh, g_Wh);
    cudaGetSymbolAddress((void**)&bqkv, g_bqkv);

    cudaFuncSetAttribute(gemm_mma_kernel<__half>,
                         cudaFuncAttributeMaxDynamicSharedMemorySize, GEMM_SMEM);
    cudaFuncSetAttribute(gemm_mma_kernel<float>,
                         cudaFuncAttributeMaxDynamicSharedMemorySize, GEMM_SMEM);

    const int n4 = MTOK * DD / 4;
    dim3 cgrid((n4 + 255) / 256);
    dim3 wgrid(DD / 32, DD / 32), wblk(32, 8);

    pack_bias_kernel<<<(NQKV + 255) / 256, 256>>>(bq, bk, bv, bqkv);       // 0
    convert_Ah_kernel<<<cgrid, 256>>>(x, Ah);                              // 1
    convert_Wh_kernel<<<wgrid, wblk>>>(Wq, Wh + 0ULL * DD * DD);           // 2
    convert_Wh_kernel<<<wgrid, wblk>>>(Wk, Wh + 1ULL * DD * DD);           // 3
    convert_Wh_kernel<<<wgrid, wblk>>>(Wv, Wh + 2ULL * DD * DD);           // 4

    // fused QKV projection: fp16 out
    dim3 qkv_grid(NQKV / GBN, MTOK / GBM);   // (24, 128)
    gemm_mma_kernel<__half><<<qkv_grid, 256, GEMM_SMEM>>>(Ah, Wh, bqkv, QKVp, NQKV);  // 5

    attn_kernel<<<MTOK / 2, 128>>>(QKVp, Ah);                              // 6

    convert_Wh_kernel<<<wgrid, wblk>>>(Wo, Wh + 3ULL * DD * DD);           // 7

    // output projection: fp32 out
    dim3 o_grid(DD / GBN, MTOK / GBM);       // (8, 128)
    gemm_mma_kernel<float><<<o_grid, 256, GEMM_SMEM>>>(Ah, Wh + 3ULL * DD * DD, bo, out, DD);  // 8
}

// round 16
// speedup vs baseline: 1.2642x; 1.0112x over previous
#include <cuda_runtime.h>
#include <cuda_fp16.h>
#include <math.h>
#include <stdint.h>

// Problem shape (fixed)
#define BB 8
#define LL 2048
#define DD 1024
#define NH 16
#define HD 64
#define MTOK (BB * LL)        // 16384 tokens
#define NQKV (3 * DD)         // 3072: fused q|k|v output width

// ======================= scratch ============================================
__device__ __half g_QKV[(size_t)MTOK * NQKV];     // 96 MB fp16 (q|k|v per row)
__device__ __half g_Ah[(size_t)MTOK * DD];        // 32 MB fp16 activations
__device__ __half g_Wh[4ULL * DD * DD];           // 8 MB fp16 weights (transposed)
__device__ float  g_bqkv[NQKV];

// ======================= small helpers ======================================
__device__ __forceinline__ uint32_t smem_u32(const void* p) {
    uint32_t a;
    asm("{ .reg .u64 t; cvta.to.shared.u64 t, %1; cvt.u32.u64 %0, t; }"
        : "=r"(a) : "l"(p));
    return a;
}
__device__ __forceinline__ void cp_async16(uint32_t dst, const void* src) {
    asm volatile("cp.async.cg.shared.global [%0], [%1], 16;" :: "r"(dst), "l"(src));
}
#define CP_COMMIT() asm volatile("cp.async.commit_group;" ::: "memory")

__device__ __forceinline__ void ldsm_x4(uint32_t* r, uint32_t addr) {
    asm volatile("ldmatrix.sync.aligned.m8n8.x4.shared.b16 {%0,%1,%2,%3}, [%4];"
                 : "=r"(r[0]), "=r"(r[1]), "=r"(r[2]), "=r"(r[3]) : "r"(addr));
}
__device__ __forceinline__ void ldsm_x4_trans(uint32_t* r, uint32_t addr) {
    asm volatile("ldmatrix.sync.aligned.m8n8.x4.trans.shared.b16 {%0,%1,%2,%3}, [%4];"
                 : "=r"(r[0]), "=r"(r[1]), "=r"(r[2]), "=r"(r[3]) : "r"(addr));
}
__device__ __forceinline__ void mma16816(float* c, const uint32_t* a,
                                         uint32_t b0, uint32_t b1) {
    asm volatile(
        "mma.sync.aligned.m16n8k16.row.col.f32.f16.f16.f32 "
        "{%0,%1,%2,%3}, {%4,%5,%6,%7}, {%8,%9}, {%0,%1,%2,%3};"
        : "+f"(c[0]), "+f"(c[1]), "+f"(c[2]), "+f"(c[3])
        : "r"(a[0]), "r"(a[1]), "r"(a[2]), "r"(a[3]), "r"(b0), "r"(b1));
}

// ======================= prep kernels (merged) ==============================
// All 4 weights: W [K=DD, N=DD] fp32 -> T [N, DD] fp16 (transposed), z = which W
__global__ void __launch_bounds__(256) prep_W_kernel(
    const float* __restrict__ Wq, const float* __restrict__ Wk,
    const float* __restrict__ Wv, const float* __restrict__ Wo,
    __half* __restrict__ T)
{
    __shared__ float t[32][33];
    const float* W = (blockIdx.z == 0) ? Wq : (blockIdx.z == 1) ? Wk
                   : (blockIdx.z == 2) ? Wv : Wo;
    __half* Tz = T + (size_t)blockIdx.z * DD * DD;
    int bx = blockIdx.x * 32, by = blockIdx.y * 32;
    int tx = threadIdx.x, ty = threadIdx.y;
    for (int j = ty; j < 32; j += 8)
        t[j][tx] = W[(size_t)(by + j) * DD + bx + tx];
    __syncthreads();
    for (int j = ty; j < 32; j += 8) {
        float v = t[tx][j];
        Tz[(size_t)(bx + j) * DD + by + tx] = __float2half_rn(v);
    }
}

// x -> fp16 Ah; first NQKV threads also pack bias
__global__ void __launch_bounds__(256) prep_A_kernel(
    const float* __restrict__ in, __half* __restrict__ out,
    const float* __restrict__ bq, const float* __restrict__ bk,
    const float* __restrict__ bv, float* __restrict__ bias_out)
{
    int i = blockIdx.x * blockDim.x + threadIdx.x;
    if (i < NQKV)
        bias_out[i] = (i < DD) ? bq[i] : (i < 2 * DD) ? bk[i - DD] : bv[i - 2 * DD];
    if (i >= MTOK * DD / 4) return;
    float4 v = reinterpret_cast<const float4*>(in)[i];
    __half2 p0 = __halves2half2(__float2half_rn(v.x), __float2half_rn(v.y));
    __half2 p1 = __halves2half2(__float2half_rn(v.z), __float2half_rn(v.w));
    uint2 u;
    u.x = *reinterpret_cast<uint32_t*>(&p0);
    u.y = *reinterpret_cast<uint32_t*>(&p1);
    reinterpret_cast<uint2*>(out)[i] = u;
}

// ======================= mma.sync GEMM ======================================
#define GBM 128
#define GBN 128
#define GBK 64
#define GSTAGES 3
#define APAD 8
#define SROW (GBK + APAD)                    // 72 fp16 = 144 B
#define TILE_BYTES (GBM * SROW * 2)          // 18432
#define STAGE_BYTES (2 * TILE_BYTES)         // 36864 (A + B)
#define GEMM_SMEM (GSTAGES * STAGE_BYTES)    // 110592
#define GNIT (DD / GBK)                      // 16

template <typename OutT>
__global__ void __launch_bounds__(256, 2) gemm_mma_kernel(
    const __half* __restrict__ A, const __half* __restrict__ B,
    const float* __restrict__ bias, OutT* __restrict__ C, int N)
{
    extern __shared__ __half sm[];
    const uint32_t sbase = smem_u32(sm);

    const int tid = threadIdx.x;
    const int lane = tid & 31;
    const int wid = tid >> 5;
    const int wm = wid & 3;
    const int wn = wid >> 2;
    const int bm = blockIdx.y * GBM;
    const int bn = blockIdx.x * GBN;

    float acc[2][8][4];
#pragma unroll
    for (int i = 0; i < 2; i++)
#pragma unroll
        for (int j = 0; j < 8; j++)
#pragma unroll
            for (int q = 0; q < 4; q++) acc[i][j][q] = 0.f;

    auto load_stage = [&](int it, int s) {
        const int kt = it * GBK;
        const uint32_t st = sbase + s * STAGE_BYTES;
#pragma unroll
        for (int i = 0; i < 4; i++) {
            int c = tid + 256 * i;
            int r = c >> 3, ch = c & 7;
            uint32_t off = (r * SROW + ch * 8) * 2;
            cp_async16(st + off,              A + (size_t)(bm + r) * DD + kt + ch * 8);
            cp_async16(st + TILE_BYTES + off, B + (size_t)(bn + r) * DD + kt + ch * 8);
        }
        CP_COMMIT();
    };

    load_stage(0, 0);
    load_stage(1, 1);

    const int a_row = wm * 32 + (lane & 15);
    const int a_kof = ((lane >> 4) & 1) * 8;
    const int b_row = wn * 64 + ((lane >> 4) & 1) * 8 + (lane & 7);
    const int b_kof = ((lane >> 3) & 1) * 8;

    uint32_t af[2][2][4], bf[2][4][4];

    auto load_frags = [&](int buf, uint32_t abase, uint32_t bbase, int k0) {
#pragma unroll
        for (int mi = 0; mi < 2; mi++)
            ldsm_x4(af[buf][mi], abase + ((a_row + mi * 16) * SROW + k0 + a_kof) * 2);
#pragma unroll
        for (int nj = 0; nj < 4; nj++)
            ldsm_x4(bf[buf][nj], bbase + ((b_row + nj * 16) * SROW + k0 + b_kof) * 2);
    };
    auto do_mmas = [&](int buf) {
#pragma unroll
        for (int mi = 0; mi < 2; mi++)
#pragma unroll
            for (int nj = 0; nj < 4; nj++) {
                mma16816(acc[mi][2 * nj],     af[buf][mi], bf[buf][nj][0], bf[buf][nj][1]);
                mma16816(acc[mi][2 * nj + 1], af[buf][mi], bf[buf][nj][2], bf[buf][nj][3]);
            }
    };

    for (int it = 0; it < GNIT; it++) {
        const int s = it % 3;
        asm volatile("cp.async.wait_group 1;" ::: "memory");
        __syncthreads();

        if (it + 2 < GNIT) load_stage(it + 2, (it + 2) % 3);
        else CP_COMMIT();

        const uint32_t abase = sbase + s * STAGE_BYTES;
        const uint32_t bbase = abase + TILE_BYTES;
        load_frags(0, abase, bbase, 0);
#pragma unroll
        for (int ks = 0; ks < 4; ks++) {
            if (ks < 3) load_frags((ks + 1) & 1, abase, bbase, (ks + 1) * 16);
            do_mmas(ks & 1);
        }
    }

#pragma unroll
    for (int mi = 0; mi < 2; mi++) {
#pragma unroll
        for (int ni = 0; ni < 8; ni++) {
            int row = bm + wm * 32 + mi * 16 + (lane >> 2);
            int col = bn + wn * 64 + ni * 8 + (lane & 3) * 2;
            float b0 = __ldg(&bias[col]), b1 = __ldg(&bias[col + 1]);
            float c00 = acc[mi][ni][0] + b0, c01 = acc[mi][ni][1] + b1;
            float c10 = acc[mi][ni][2] + b0, c11 = acc[mi][ni][3] + b1;
            if constexpr (sizeof(OutT) == 4) {
                float2 v0 = {c00, c01}, v1 = {c10, c11};
                *reinterpret_cast<float2*>(&C[(size_t)row * N + col]) = v0;
                *reinterpret_cast<float2*>(&C[(size_t)(row + 8) * N + col]) = v1;
            } else {
                __half2 h0 = __floats2half2_rn(c00, c01);
                __half2 h1 = __floats2half2_rn(c10, c11);
                *reinterpret_cast<__half2*>(&C[(size_t)row * N + col]) = h0;
                *reinterpret_cast<__half2*>(&C[(size_t)(row + 8) * N + col]) = h1;
            }
        }
    }
}

// ======================= tensor-core attention ==============================
// 2 tokens per 128-thread block; 2 warps per token (row halves 0-31 / 32-63).
#define SROW2 24                       // 16 halves + 8 pad
#define TTILE (64 * SROW2)             // 1536 halves per padded 64x16 tile

__global__ void __launch_bounds__(128) attn_kernel(
    const __half* __restrict__ QKV, __half* __restrict__ Ah)
{
    __shared__ __half sm2[2 * 3 * TTILE];   // 2 tokens x {q,k,v}, 18432 B

    const int tid = threadIdx.x;
    const int lane = tid & 31;
    const int wid = tid >> 5;          // 0..3
    const int tokL = wid >> 1;         // token within block
    const int hm = wid & 1;            // row half (0: rows 0-31, 1: 32-63)
    const int t0 = blockIdx.x * 2;

    // stage 2 tokens x 3 mats x 128 uint4 chunks (16B each)
    for (int c = tid; c < 768; c += 128) {
        int tk = c / 384;
        int rem = c - tk * 384;
        int mat = rem >> 7;
        int ch = rem & 127;
        int row = ch >> 1, part = ch & 1;
        uint4 v = *reinterpret_cast<const uint4*>(
            QKV + (size_t)(t0 + tk) * NQKV + mat * DD + row * 16 + part * 8);
        *reinterpret_cast<uint4*>(
            &sm2[tk * 3 * TTILE + mat * TTILE + row * SROW2 + part * 8]) = v;
    }
    __syncthreads();

    const uint32_t qb = smem_u32(&sm2[tokL * 3 * TTILE]);
    const uint32_t kb = qb + TTILE * 2;
    const uint32_t vb = qb + 2 * TTILE * 2;

    // ---- S = q @ k^T ----
    uint32_t aq[2][4];
#pragma unroll
    for (int mi = 0; mi < 2; mi++) {
        int r = hm * 32 + mi * 16 + (lane & 15);
        ldsm_x4(aq[mi], qb + (r * SROW2 + ((lane >> 4) & 1) * 8) * 2);
    }
    uint32_t bk[4][4];
#pragma unroll
    for (int nj = 0; nj < 4; nj++) {
        int r = nj * 16 + ((lane >> 4) & 1) * 8 + (lane & 7);
        ldsm_x4(bk[nj], kb + (r * SROW2 + ((lane >> 3) & 1) * 8) * 2);
    }
    float acc[2][8][4];
#pragma unroll
    for (int mi = 0; mi < 2; mi++)
#pragma unroll
        for (int ni = 0; ni < 8; ni++)
#pragma unroll
            for (int q = 0; q < 4; q++) acc[mi][ni][q] = 0.f;
#pragma unroll
    for (int mi = 0; mi < 2; mi++)
#pragma unroll
        for (int nj = 0; nj < 4; nj++) {
            mma16816(acc[mi][2 * nj],     aq[mi], bk[nj][0], bk[nj][1]);
            mma16816(acc[mi][2 * nj + 1], aq[mi], bk[nj][2], bk[nj][3]);
        }

    // ---- V fragments (trans) ----
    uint32_t bv[4][4];
#pragma unroll
    for (int kt = 0; kt < 4; kt++) {
        int r = kt * 16 + ((lane >> 3) & 1) * 8 + (lane & 7);
        ldsm_x4_trans(bv[kt], vb + (r * SROW2 + ((lane >> 4) & 1) * 8) * 2);
    }

    // ---- mask + softmax + P(fp16) + PV per m-tile ----
    float accO[2][2][4];
#pragma unroll
    for (int mi = 0; mi < 2; mi++)
#pragma unroll
        for (int nt = 0; nt < 2; nt++)
#pragma unroll
            for (int q = 0; q < 4; q++) accO[mi][nt][q] = 0.f;

    const int rlo = hm * 32 + (lane >> 2);
    const int cbase = (lane & 3) * 2;

#pragma unroll
    for (int mi = 0; mi < 2; mi++) {
        int r0 = rlo + mi * 16;
        int r1 = r0 + 8;
        float mx0 = -INFINITY, mx1 = -INFINITY;
#pragma unroll
        for (int ni = 0; ni < 8; ni++) {
            int j0 = ni * 8 + cbase, j1 = j0 + 1;
            float v0 = acc[mi][ni][0] * 0.25f + 1e-6f;
            float v1 = acc[mi][ni][1] * 0.25f + 1e-6f;
            float v2 = acc[mi][ni][2] * 0.25f + 1e-6f;
            float v3 = acc[mi][ni][3] * 0.25f + 1e-6f;
            acc[mi][ni][0] = (j0 <= r0 && v0 != 0.f) ? v0 : -INFINITY;
            acc[mi][ni][1] = (j1 <= r0 && v1 != 0.f) ? v1 : -INFINITY;
            acc[mi][ni][2] = (j0 <= r1 && v2 != 0.f) ? v2 : -INFINITY;
            acc[mi][ni][3] = (j1 <= r1 && v3 != 0.f) ? v3 : -INFINITY;
            mx0 = fmaxf(mx0, fmaxf(acc[mi][ni][0], acc[mi][ni][1]));
            mx1 = fmaxf(mx1, fmaxf(acc[mi][ni][2], acc[mi][ni][3]));
        }
        mx0 = fmaxf(mx0, __shfl_xor_sync(0xFFFFFFFF, mx0, 1));
        mx0 = fmaxf(mx0, __shfl_xor_sync(0xFFFFFFFF, mx0, 2));
        mx1 = fmaxf(mx1, __shfl_xor_sync(0xFFFFFFFF, mx1, 1));
        mx1 = fmaxf(mx1, __shfl_xor_sync(0xFFFFFFFF, mx1, 2));

        float s0 = 0.f, s1 = 0.f;
#pragma unroll
        for (int ni = 0; ni < 8; ni++) {
            float e0 = __expf(acc[mi][ni][0] - mx0);
            float e1 = __expf(acc[mi][ni][1] - mx0);
            float e2 = __expf(acc[mi][ni][2] - mx1);
            float e3 = __expf(acc[mi][ni][3] - mx1);
            acc[mi][ni][0] = e0; acc[mi][ni][1] = e1;
            acc[mi][ni][2] = e2; acc[mi][ni][3] = e3;
            s0 += e0 + e1; s1 += e2 + e3;
        }
        s0 += __shfl_xor_sync(0xFFFFFFFF, s0, 1);
        s0 += __shfl_xor_sync(0xFFFFFFFF, s0, 2);
        s1 += __shfl_xor_sync(0xFFFFFFFF, s1, 1);
        s1 += __shfl_xor_sync(0xFFFFFFFF, s1, 2);
        float inv0 = 1.f / s0, inv1 = 1.f / s1;

#pragma unroll
        for (int kt = 0; kt < 4; kt++) {
            uint32_t aP[4];
            __half2 h;
            h = __floats2half2_rn(acc[mi][2 * kt][0] * inv0, acc[mi][2 * kt][1] * inv0);
            aP[0] = *reinterpret_cast<uint32_t*>(&h);
            h = __floats2half2_rn(acc[mi][2 * kt][2] * inv1, acc[mi][2 * kt][3] * inv1);
            aP[1] = *reinterpret_cast<uint32_t*>(&h);
            h = __floats2half2_rn(acc[mi][2 * kt + 1][0] * inv0, acc[mi][2 * kt + 1][1] * inv0);
            aP[2] = *reinterpret_cast<uint32_t*>(&h);
            h = __floats2half2_rn(acc[mi][2 * kt + 1][2] * inv1, acc[mi][2 * kt + 1][3] * inv1);
            aP[3] = *reinterpret_cast<uint32_t*>(&h);
#pragma unroll
            for (int nt = 0; nt < 2; nt++)
                mma16816(accO[mi][nt], aP, bv[kt][nt * 2], bv[kt][nt * 2 + 1]);
        }
    }

    // ---- store O (fp16) ----
    __half* ob = Ah + (size_t)(t0 + tokL) * DD;
#pragma unroll
    for (int mi = 0; mi < 2; mi++) {
        int r0 = rlo + mi * 16;
#pragma unroll
        for (int nt = 0; nt < 2; nt++) {
            int col = nt * 8 + cbase;
            __half2 h0 = __floats2half2_rn(accO[mi][nt][0], accO[mi][nt][1]);
            __half2 h1 = __floats2half2_rn(accO[mi][nt][2], accO[mi][nt][3]);
            *reinterpret_cast<__half2*>(ob + r0 * 16 + col) = h0;
            *reinterpret_cast<__half2*>(ob + (r0 + 8) * 16 + col) = h1;
        }
    }
}

// ======================= launch =============================================
extern "C" void kernel_launch(void* const* d_in, const int* in_sizes, int n_in,
                              void* d_out, int out_size)
{
    const float* x  = (const float*)d_in[0];
    const float* Wq = (const float*)d_in[1];
    const float* bq = (const float*)d_in[2];
    const float* Wk = (const float*)d_in[3];
    const float* bk = (const float*)d_in[4];
    const float* Wv = (const float*)d_in[5];
    const float* bv = (const float*)d_in[6];
    const float* Wo = (const float*)d_in[7];
    const float* bo = (const float*)d_in[8];
    float* out = (float*)d_out;

    float *bqkv;
    __half *QKVp, *Ah, *Wh;
    cudaGetSymbolAddress((void**)&QKVp, g_QKV);
    cudaGetSymbolAddress((void**)&Ah, g_Ah);
    cudaGetSymbolAddress((void**)&Wh, g_Wh);
    cudaGetSymbolAddress((void**)&bqkv, g_bqkv);

    cudaFuncSetAttribute(gemm_mma_kernel<__half>,
                         cudaFuncAttributeMaxDynamicSharedMemorySize, GEMM_SMEM);
    cudaFuncSetAttribute(gemm_mma_kernel<float>,
                         cudaFuncAttributeMaxDynamicSharedMemorySize, GEMM_SMEM);

    const int n4 = MTOK * DD / 4;
    dim3 cgrid((n4 + 255) / 256);
    dim3 wgrid(DD / 32, DD / 32, 4), wblk(32, 8);

    // merged prep: 2 launches instead of 6
    prep_W_kernel<<<wgrid, wblk>>>(Wq, Wk, Wv, Wo, Wh);                    // 0
    prep_A_kernel<<<cgrid, 256>>>(x, Ah, bq, bk, bv, bqkv);                // 1

    // fused QKV projection: fp16 out
    dim3 qkv_grid(NQKV / GBN, MTOK / GBM);   // (24, 128)
    gemm_mma_kernel<__half><<<qkv_grid, 256, GEMM_SMEM>>>(Ah, Wh, bqkv, QKVp, NQKV);  // 2

    attn_kernel<<<MTOK / 2, 128>>>(QKVp, Ah);                              // 3

    // output projection: fp32 out
    dim3 o_grid(DD / GBN, MTOK / GBM);       // (8, 128)
    gemm_mma_kernel<float><<<o_grid, 256, GEMM_SMEM>>>(Ah, Wh + 3ULL * DD * DD, bo, out, DD);  // 4
}

// round 17
// speedup vs baseline: 1.2737x; 1.0075x over previous
#include <cuda_runtime.h>
#include <cuda_fp16.h>
#include <math.h>
#include <stdint.h>

// Problem shape (fixed)
#define BB 8
#define LL 2048
#define DD 1024
#define NH 16
#define HD 64
#define MTOK (BB * LL)        // 16384 tokens
#define NQKV (3 * DD)         // 3072: fused q|k|v output width

// ======================= scratch ============================================
__device__ __half g_QKV[(size_t)MTOK * NQKV];     // 96 MB fp16 (q|k|v per row)
__device__ __half g_Ah[(size_t)MTOK * DD];        // 32 MB fp16 activations
__device__ __half g_Wh[4ULL * DD * DD];           // 8 MB fp16 weights (transposed)
__device__ float  g_bqkv[NQKV];

// ======================= small helpers ======================================
__device__ __forceinline__ uint32_t smem_u32(const void* p) {
    uint32_t a;
    asm("{ .reg .u64 t; cvta.to.shared.u64 t, %1; cvt.u32.u64 %0, t; }"
        : "=r"(a) : "l"(p));
    return a;
}
__device__ __forceinline__ void cp_async16(uint32_t dst, const void* src) {
    asm volatile("cp.async.cg.shared.global [%0], [%1], 16;" :: "r"(dst), "l"(src));
}
#define CP_COMMIT() asm volatile("cp.async.commit_group;" ::: "memory")

__device__ __forceinline__ void ldsm_x4(uint32_t* r, uint32_t addr) {
    asm volatile("ldmatrix.sync.aligned.m8n8.x4.shared.b16 {%0,%1,%2,%3}, [%4];"
                 : "=r"(r[0]), "=r"(r[1]), "=r"(r[2]), "=r"(r[3]) : "r"(addr));
}
__device__ __forceinline__ void ldsm_x4_trans(uint32_t* r, uint32_t addr) {
    asm volatile("ldmatrix.sync.aligned.m8n8.x4.trans.shared.b16 {%0,%1,%2,%3}, [%4];"
                 : "=r"(r[0]), "=r"(r[1]), "=r"(r[2]), "=r"(r[3]) : "r"(addr));
}
__device__ __forceinline__ void mma16816(float* c, const uint32_t* a,
                                         uint32_t b0, uint32_t b1) {
    asm volatile(
        "mma.sync.aligned.m16n8k16.row.col.f32.f16.f16.f32 "
        "{%0,%1,%2,%3}, {%4,%5,%6,%7}, {%8,%9}, {%0,%1,%2,%3};"
        : "+f"(c[0]), "+f"(c[1]), "+f"(c[2]), "+f"(c[3])
        : "r"(a[0]), "r"(a[1]), "r"(a[2]), "r"(a[3]), "r"(b0), "r"(b1));
}

// ======================= prep kernels (merged) ==============================
__global__ void __launch_bounds__(256) prep_W_kernel(
    const float* __restrict__ Wq, const float* __restrict__ Wk,
    const float* __restrict__ Wv, const float* __restrict__ Wo,
    __half* __restrict__ T)
{
    __shared__ float t[32][33];
    const float* W = (blockIdx.z == 0) ? Wq : (blockIdx.z == 1) ? Wk
                   : (blockIdx.z == 2) ? Wv : Wo;
    __half* Tz = T + (size_t)blockIdx.z * DD * DD;
    int bx = blockIdx.x * 32, by = blockIdx.y * 32;
    int tx = threadIdx.x, ty = threadIdx.y;
    for (int j = ty; j < 32; j += 8)
        t[j][tx] = W[(size_t)(by + j) * DD + bx + tx];
    __syncthreads();
    for (int j = ty; j < 32; j += 8) {
        float v = t[tx][j];
        Tz[(size_t)(bx + j) * DD + by + tx] = __float2half_rn(v);
    }
}

__global__ void __launch_bounds__(256) prep_A_kernel(
    const float* __restrict__ in, __half* __restrict__ out,
    const float* __restrict__ bq, const float* __restrict__ bk,
    const float* __restrict__ bv, float* __restrict__ bias_out)
{
    int i = blockIdx.x * blockDim.x + threadIdx.x;
    if (i < NQKV)
        bias_out[i] = (i < DD) ? bq[i] : (i < 2 * DD) ? bk[i - DD] : bv[i - 2 * DD];
    if (i >= MTOK * DD / 4) return;
    float4 v = reinterpret_cast<const float4*>(in)[i];
    __half2 p0 = __halves2half2(__float2half_rn(v.x), __float2half_rn(v.y));
    __half2 p1 = __halves2half2(__float2half_rn(v.z), __float2half_rn(v.w));
    uint2 u;
    u.x = *reinterpret_cast<uint32_t*>(&p0);
    u.y = *reinterpret_cast<uint32_t*>(&p1);
    reinterpret_cast<uint2*>(out)[i] = u;
}

// ======================= mma.sync GEMM ======================================
#define GBM 128
#define GBN 128
#define GBK 64
#define GSTAGES 3
#define APAD 8
#define SROW (GBK + APAD)                    // 72 fp16 = 144 B
#define TILE_BYTES (GBM * SROW * 2)          // 18432
#define STAGE_BYTES (2 * TILE_BYTES)         // 36864 (A + B)
#define GEMM_SMEM (GSTAGES * STAGE_BYTES)    // 110592
#define GNIT (DD / GBK)                      // 16

template <typename OutT>
__global__ void __launch_bounds__(256, 2) gemm_mma_kernel(
    const __half* __restrict__ A, const __half* __restrict__ B,
    const float* __restrict__ bias, OutT* __restrict__ C, int N)
{
    extern __shared__ __half sm[];
    const uint32_t sbase = smem_u32(sm);

    const int tid = threadIdx.x;
    const int lane = tid & 31;
    const int wid = tid >> 5;
    const int wm = wid & 3;
    const int wn = wid >> 2;
    const int bm = blockIdx.y * GBM;
    const int bn = blockIdx.x * GBN;

    float acc[2][8][4];
#pragma unroll
    for (int i = 0; i < 2; i++)
#pragma unroll
        for (int j = 0; j < 8; j++)
#pragma unroll
            for (int q = 0; q < 4; q++) acc[i][j][q] = 0.f;

    auto load_stage = [&](int it, int s) {
        const int kt = it * GBK;
        const uint32_t st = sbase + s * STAGE_BYTES;
#pragma unroll
        for (int i = 0; i < 4; i++) {
            int c = tid + 256 * i;
            int r = c >> 3, ch = c & 7;
            uint32_t off = (r * SROW + ch * 8) * 2;
            cp_async16(st + off,              A + (size_t)(bm + r) * DD + kt + ch * 8);
            cp_async16(st + TILE_BYTES + off, B + (size_t)(bn + r) * DD + kt + ch * 8);
        }
        CP_COMMIT();
    };

    load_stage(0, 0);
    load_stage(1, 1);

    const int a_row = wm * 32 + (lane & 15);
    const int a_kof = ((lane >> 4) & 1) * 8;
    const int b_row = wn * 64 + ((lane >> 4) & 1) * 8 + (lane & 7);
    const int b_kof = ((lane >> 3) & 1) * 8;

    uint32_t af[2][2][4], bf[2][4][4];

    auto load_frags = [&](int buf, uint32_t abase, uint32_t bbase, int k0) {
#pragma unroll
        for (int mi = 0; mi < 2; mi++)
            ldsm_x4(af[buf][mi], abase + ((a_row + mi * 16) * SROW + k0 + a_kof) * 2);
#pragma unroll
        for (int nj = 0; nj < 4; nj++)
            ldsm_x4(bf[buf][nj], bbase + ((b_row + nj * 16) * SROW + k0 + b_kof) * 2);
    };
    auto do_mmas = [&](int buf) {
#pragma unroll
        for (int mi = 0; mi < 2; mi++)
#pragma unroll
            for (int nj = 0; nj < 4; nj++) {
                mma16816(acc[mi][2 * nj],     af[buf][mi], bf[buf][nj][0], bf[buf][nj][1]);
                mma16816(acc[mi][2 * nj + 1], af[buf][mi], bf[buf][nj][2], bf[buf][nj][3]);
            }
    };

    for (int it = 0; it < GNIT; it++) {
        const int s = it % 3;
        asm volatile("cp.async.wait_group 1;" ::: "memory");
        __syncthreads();

        if (it + 2 < GNIT) load_stage(it + 2, (it + 2) % 3);
        else CP_COMMIT();

        const uint32_t abase = sbase + s * STAGE_BYTES;
        const uint32_t bbase = abase + TILE_BYTES;
        load_frags(0, abase, bbase, 0);
#pragma unroll
        for (int ks = 0; ks < 4; ks++) {
            if (ks < 3) load_frags((ks + 1) & 1, abase, bbase, (ks + 1) * 16);
            do_mmas(ks & 1);
        }
    }

#pragma unroll
    for (int mi = 0; mi < 2; mi++) {
#pragma unroll
        for (int ni = 0; ni < 8; ni++) {
            int row = bm + wm * 32 + mi * 16 + (lane >> 2);
            int col = bn + wn * 64 + ni * 8 + (lane & 3) * 2;
            float b0 = __ldg(&bias[col]), b1 = __ldg(&bias[col + 1]);
            float c00 = acc[mi][ni][0] + b0, c01 = acc[mi][ni][1] + b1;
            float c10 = acc[mi][ni][2] + b0, c11 = acc[mi][ni][3] + b1;
            if constexpr (sizeof(OutT) == 4) {
                float2 v0 = {c00, c01}, v1 = {c10, c11};
                *reinterpret_cast<float2*>(&C[(size_t)row * N + col]) = v0;
                *reinterpret_cast<float2*>(&C[(size_t)(row + 8) * N + col]) = v1;
            } else {
                __half2 h0 = __floats2half2_rn(c00, c01);
                __half2 h1 = __floats2half2_rn(c10, c11);
                *reinterpret_cast<__half2*>(&C[(size_t)row * N + col]) = h0;
                *reinterpret_cast<__half2*>(&C[(size_t)(row + 8) * N + col]) = h1;
            }
        }
    }
}

// ======================= tensor-core attention ==============================
// 2 tokens per 128-thread block; 2 warps per token (row halves 0-31 / 32-63).
// No max-subtraction (scores bounded); mask+exp fused; normalization deferred
// to the O accumulators (16 mults instead of 64).
#define SROW2 24                       // 16 halves + 8 pad
#define TTILE (64 * SROW2)             // 1536 halves per padded 64x16 tile

__global__ void __launch_bounds__(128) attn_kernel(
    const __half* __restrict__ QKV, __half* __restrict__ Ah)
{
    __shared__ __half sm2[2 * 3 * TTILE];   // 2 tokens x {q,k,v}, 18432 B

    const int tid = threadIdx.x;
    const int lane = tid & 31;
    const int wid = tid >> 5;          // 0..3
    const int tokL = wid >> 1;         // token within block
    const int hm = wid & 1;            // row half (0: rows 0-31, 1: 32-63)
    const int t0 = blockIdx.x * 2;

    // stage 2 tokens x 3 mats x 128 uint4 chunks (16B each)
    for (int c = tid; c < 768; c += 128) {
        int tk = c / 384;
        int rem = c - tk * 384;
        int mat = rem >> 7;
        int ch = rem & 127;
        int row = ch >> 1, part = ch & 1;
        uint4 v = *reinterpret_cast<const uint4*>(
            QKV + (size_t)(t0 + tk) * NQKV + mat * DD + row * 16 + part * 8);
        *reinterpret_cast<uint4*>(
            &sm2[tk * 3 * TTILE + mat * TTILE + row * SROW2 + part * 8]) = v;
    }
    __syncthreads();

    const uint32_t qb = smem_u32(&sm2[tokL * 3 * TTILE]);
    const uint32_t kb = qb + TTILE * 2;
    const uint32_t vb = qb + 2 * TTILE * 2;

    // ---- S = q @ k^T ----
    uint32_t aq[2][4];
#pragma unroll
    for (int mi = 0; mi < 2; mi++) {
        int r = hm * 32 + mi * 16 + (lane & 15);
        ldsm_x4(aq[mi], qb + (r * SROW2 + ((lane >> 4) & 1) * 8) * 2);
    }
    uint32_t bk[4][4];
#pragma unroll
    for (int nj = 0; nj < 4; nj++) {
        int r = nj * 16 + ((lane >> 4) & 1) * 8 + (lane & 7);
        ldsm_x4(bk[nj], kb + (r * SROW2 + ((lane >> 3) & 1) * 8) * 2);
    }
    float acc[2][8][4];
#pragma unroll
    for (int mi = 0; mi < 2; mi++)
#pragma unroll
        for (int ni = 0; ni < 8; ni++)
#pragma unroll
            for (int q = 0; q < 4; q++) acc[mi][ni][q] = 0.f;
#pragma unroll
    for (int mi = 0; mi < 2; mi++)
#pragma unroll
        for (int nj = 0; nj < 4; nj++) {
            mma16816(acc[mi][2 * nj],     aq[mi], bk[nj][0], bk[nj][1]);
            mma16816(acc[mi][2 * nj + 1], aq[mi], bk[nj][2], bk[nj][3]);
        }

    // ---- V fragments (trans) ----
    uint32_t bv[4][4];
#pragma unroll
    for (int kt = 0; kt < 4; kt++) {
        int r = kt * 16 + ((lane >> 3) & 1) * 8 + (lane & 7);
        ldsm_x4_trans(bv[kt], vb + (r * SROW2 + ((lane >> 4) & 1) * 8) * 2);
    }

    // ---- fused mask+exp, unnormalized P, PV, deferred normalization ----
    float accO[2][2][4];
#pragma unroll
    for (int mi = 0; mi < 2; mi++)
#pragma unroll
        for (int nt = 0; nt < 2; nt++)
#pragma unroll
            for (int q = 0; q < 4; q++) accO[mi][nt][q] = 0.f;

    const int rlo = hm * 32 + (lane >> 2);
    const int cbase = (lane & 3) * 2;

#pragma unroll
    for (int mi = 0; mi < 2; mi++) {
        int r0 = rlo + mi * 16;
        int r1 = r0 + 8;
        float s0 = 0.f, s1 = 0.f;
#pragma unroll
        for (int ni = 0; ni < 8; ni++) {
            int j0 = ni * 8 + cbase, j1 = j0 + 1;
            float v0 = fmaf(acc[mi][ni][0], 0.25f, 1e-6f);
            float v1 = fmaf(acc[mi][ni][1], 0.25f, 1e-6f);
            float v2 = fmaf(acc[mi][ni][2], 0.25f, 1e-6f);
            float v3 = fmaf(acc[mi][ni][3], 0.25f, 1e-6f);
            float e0 = (j0 <= r0 && v0 != 0.f) ? __expf(v0) : 0.f;
            float e1 = (j1 <= r0 && v1 != 0.f) ? __expf(v1) : 0.f;
            float e2 = (j0 <= r1 && v2 != 0.f) ? __expf(v2) : 0.f;
            float e3 = (j1 <= r1 && v3 != 0.f) ? __expf(v3) : 0.f;
            acc[mi][ni][0] = e0; acc[mi][ni][1] = e1;
            acc[mi][ni][2] = e2; acc[mi][ni][3] = e3;
            s0 += e0 + e1; s1 += e2 + e3;
        }
        s0 += __shfl_xor_sync(0xFFFFFFFF, s0, 1);
        s0 += __shfl_xor_sync(0xFFFFFFFF, s0, 2);
        s1 += __shfl_xor_sync(0xFFFFFFFF, s1, 1);
        s1 += __shfl_xor_sync(0xFFFFFFFF, s1, 2);
        float inv0 = 1.f / s0, inv1 = 1.f / s1;

        // unnormalized P -> fp16 A-fragments, PV accumulate
#pragma unroll
        for (int kt = 0; kt < 4; kt++) {
            uint32_t aP[4];
            __half2 h;
            h = __floats2half2_rn(acc[mi][2 * kt][0], acc[mi][2 * kt][1]);
            aP[0] = *reinterpret_cast<uint32_t*>(&h);
            h = __floats2half2_rn(acc[mi][2 * kt][2], acc[mi][2 * kt][3]);
            aP[1] = *reinterpret_cast<uint32_t*>(&h);
            h = __floats2half2_rn(acc[mi][2 * kt + 1][0], acc[mi][2 * kt + 1][1]);
            aP[2] = *reinterpret_cast<uint32_t*>(&h);
            h = __floats2half2_rn(acc[mi][2 * kt + 1][2], acc[mi][2 * kt + 1][3]);
            aP[3] = *reinterpret_cast<uint32_t*>(&h);
#pragma unroll
            for (int nt = 0; nt < 2; nt++)
                mma16816(accO[mi][nt], aP, bv[kt][nt * 2], bv[kt][nt * 2 + 1]);
        }
        // deferred normalization: scale O rows by 1/rowsum
#pragma unroll
        for (int nt = 0; nt < 2; nt++) {
            accO[mi][nt][0] *= inv0; accO[mi][nt][1] *= inv0;
            accO[mi][nt][2] *= inv1; accO[mi][nt][3] *= inv1;
        }
    }

    // ---- store O (fp16) ----
    __half* ob = Ah + (size_t)(t0 + tokL) * DD;
#pragma unroll
    for (int mi = 0; mi < 2; mi++) {
        int r0 = rlo + mi * 16;
#pragma unroll
        for (int nt = 0; nt < 2; nt++) {
            int col = nt * 8 + cbase;
            __half2 h0 = __floats2half2_rn(accO[mi][nt][0], accO[mi][nt][1]);
            __half2 h1 = __floats2half2_rn(accO[mi][nt][2], accO[mi][nt][3]);
            *reinterpret_cast<__half2*>(ob + r0 * 16 + col) = h0;
            *reinterpret_cast<__half2*>(ob + (r0 + 8) * 16 + col) = h1;
        }
    }
}

// ======================= launch =============================================
extern "C" void kernel_launch(void* const* d_in, const int* in_sizes, int n_in,
                              void* d_out, int out_size)
{
    const float* x  = (const float*)d_in[0];
    const float* Wq = (const float*)d_in[1];
    const float* bq = (const float*)d_in[2];
    const float* Wk = (const float*)d_in[3];
    const float* bk = (const float*)d_in[4];
    const float* Wv = (const float*)d_in[5];
    const float* bv = (const float*)d_in[6];
    const float* Wo = (const float*)d_in[7];
    const float* bo = (const float*)d_in[8];
    float* out = (float*)d_out;

    float *bqkv;
    __half *QKVp, *Ah, *Wh;
    cudaGetSymbolAddress((void**)&QKVp, g_QKV);
    cudaGetSymbolAddress((void**)&Ah, g_Ah);
    cudaGetSymbolAddress((void**)&Wh, g_Wh);
    cudaGetSymbolAddress((void**)&bqkv, g_bqkv);

    cudaFuncSetAttribute(gemm_mma_kernel<__half>,
                         cudaFuncAttributeMaxDynamicSharedMemorySize, GEMM_SMEM);
    cudaFuncSetAttribute(gemm_mma_kernel<float>,
                         cudaFuncAttributeMaxDynamicSharedMemorySize, GEMM_SMEM);

    const int n4 = MTOK * DD / 4;
    dim3 cgrid((n4 + 255) / 256);
    dim3 wgrid(DD / 32, DD / 32, 4), wblk(32, 8);

    prep_W_kernel<<<wgrid, wblk>>>(Wq, Wk, Wv, Wo, Wh);                    // 0
    prep_A_kernel<<<cgrid, 256>>>(x, Ah, bq, bk, bv, bqkv);                // 1

    dim3 qkv_grid(NQKV / GBN, MTOK / GBM);   // (24, 128)
    gemm_mma_kernel<__half><<<qkv_grid, 256, GEMM_SMEM>>>(Ah, Wh, bqkv, QKVp, NQKV);  // 2

    attn_kernel<<<MTOK / 2, 128>>>(QKVp, Ah);                              // 3

    dim3 o_grid(DD / GBN, MTOK / GBM);       // (8, 128)
    gemm_mma_kernel<float><<<o_grid, 256, GEMM_SMEM>>>(Ah, Wh + 3ULL * DD * DD, bo, out, DD);  // 4
}